// round 14
// baseline (speedup 1.0000x reference)
#include <cuda_runtime.h>

// SAGAN self-attention block:
//   out = x + gamma * conv_o( softmax(theta(x) @ phi(x)^T) @ g(x) )
// with spectral-normalized 1x1 convs and 2x2 maxpool on phi/g.
//
// FINAL converged kernel (4 consecutive benches at 8.672us, the session
// floor). Floor model (R2-R13, 12 benches): wall = fixed graph-replay/launch
// cost + warm L2-rate 32MB copy; all controllable axes (node count, CTA
// count/shape, MLP, addressing, cache hints, CE memcpy, speculative
// prologue) tested and exhausted. Node-count reduction 6->1 was the only
// effective lever (15.1 -> 8.67us).
//
//   gamma == 0  -> out = x: gamma + first 4 float4 loads issued together
//                  (hides gamma's L2 hit), block-contiguous addressing
//                  (each block streams one 512KB region, warp-coalesced).
//   gamma != 0  -> persistent heavy path: per-block spectral-norm into smem,
//                  projections, software grid barrier (256 co-resident
//                  blocks), flash attention, barrier, output conv+residual.
//
// No per-thread array exceeds 8 statically-indexed floats -> no local-memory
// spill (harness counts driver local-pool growth as an allocation).

#define Bx 16
#define Hh 64
#define Ww 64
#define Cc 64
#define HW 4096     // Hh*Ww
#define Mm 1024     // pooled positions (HW/4)
#define CK 8        // Cc/8
#define CG 32       // Cc/2

#define NB 256      // blocks
#define NT 512      // threads per block
#define GSZ (NB * NT)          // 131072
#define CHUNK (8 * NT)         // float4s per block: 4096

__device__ float g_theta[(size_t)Bx * HW * CK];
__device__ float g_phi[(size_t)Bx * Mm * CK];
__device__ float g_gv[(size_t)Bx * Mm * CG];
__device__ float g_attng[(size_t)Bx * HW * CG];

__device__ unsigned int g_bar_cnt = 0;
__device__ unsigned int g_bar_gen = 0;

// Software grid barrier (all NB blocks co-resident). Self-resetting so graph
// replays are deterministic.
__device__ __forceinline__ void grid_barrier() {
    __syncthreads();
    if (threadIdx.x == 0) {
        volatile unsigned int* vgen = &g_bar_gen;
        unsigned int gen = *vgen;
        __threadfence();
        if (atomicAdd(&g_bar_cnt, 1u) == NB - 1) {
            g_bar_cnt = 0;
            __threadfence();
            atomicAdd(&g_bar_gen, 1u);
        } else {
            while (*vgen == gen) {}
        }
        __threadfence();
    }
    __syncthreads();
}

// Block-cooperative spectral normalization of one [d, co] weight into smem:
//   v = l2(W @ u); u2 = l2(W^T @ v); sigma = v . (W @ u2); wbar = W / sigma
__device__ __forceinline__ void block_sn(const float* __restrict__ w,
                                         const float* __restrict__ u,
                                         int d, int co,
                                         float* __restrict__ wbar,
                                         float* __restrict__ v,
                                         float* __restrict__ u2,
                                         float* __restrict__ sigma) {
    int tid = threadIdx.x;
    if (tid < d) {
        float s = 0.f;
        for (int j = 0; j < co; j++) s += w[tid * co + j] * u[j];
        v[tid] = s;
    }
    __syncthreads();
    if (tid == 0) {
        float nr = 0.f;
        for (int i = 0; i < d; i++) nr += v[i] * v[i];
        nr = sqrtf(nr) + 1e-12f;
        for (int i = 0; i < d; i++) v[i] /= nr;
    }
    __syncthreads();
    if (tid < co) {
        float s = 0.f;
        for (int i = 0; i < d; i++) s += w[i * co + tid] * v[i];
        u2[tid] = s;
    }
    __syncthreads();
    if (tid == 0) {
        float nr = 0.f;
        for (int j = 0; j < co; j++) nr += u2[j] * u2[j];
        nr = sqrtf(nr) + 1e-12f;
        float sig = 0.f;
        for (int i = 0; i < d; i++) {
            float t = 0.f;
            for (int j = 0; j < co; j++) t += w[i * co + j] * (u2[j] / nr);
            sig += v[i] * t;
        }
        *sigma = sig;
    }
    __syncthreads();
    float inv_sig = 1.0f / (*sigma);
    for (int e = tid; e < d * co; e += NT) wbar[e] = w[e] * inv_sig;
    __syncthreads();
}

__global__ void __launch_bounds__(NT) k_fused(
        const float* __restrict__ x,
        const float* __restrict__ w_theta, const float* __restrict__ u_theta,
        const float* __restrict__ w_phi,   const float* __restrict__ u_phi,
        const float* __restrict__ w_g,     const float* __restrict__ u_g,
        const float* __restrict__ w_o,     const float* __restrict__ u_o,
        const float* __restrict__ gamma,
        float* __restrict__ out) {
    const int tid = threadIdx.x;
    const int gtid = blockIdx.x * NT + tid;

    const float4* __restrict__ xi = reinterpret_cast<const float4*>(x);
    float4* __restrict__ oo = reinterpret_cast<float4*>(out);

    // Speculative prologue: gamma + first 4 block-contiguous loads in flight
    // together (loads are side-effect free; valid on both paths).
    const int cbase = blockIdx.x * CHUNK + tid;
    const float gm = gamma[0];
    float4 v0 = xi[cbase + 0 * NT];
    float4 v1 = xi[cbase + 1 * NT];
    float4 v2 = xi[cbase + 2 * NT];
    float4 v3 = xi[cbase + 3 * NT];
    // NB*CHUNK = 256*4096 = 1,048,576 = Bx*HW*Cc/4 exactly.

    if (gm == 0.0f) {
        // ---------- fast path: out = x, block-contiguous copy ----------
        oo[cbase + 0 * NT] = v0;
        oo[cbase + 1 * NT] = v1;
        float4 v4 = xi[cbase + 4 * NT];
        float4 v5 = xi[cbase + 5 * NT];
        float4 v6 = xi[cbase + 6 * NT];
        float4 v7 = xi[cbase + 7 * NT];
        oo[cbase + 2 * NT] = v2;
        oo[cbase + 3 * NT] = v3;
        oo[cbase + 4 * NT] = v4;
        oo[cbase + 5 * NT] = v5;
        oo[cbase + 6 * NT] = v6;
        oo[cbase + 7 * NT] = v7;
        return;
    }

    // ---------- heavy path (gamma != 0) ----------
    __shared__ float sbuf[3072];           // reused per phase (12 KB)
    __shared__ float sv[64], su2[64], ssig;

    // ===== Phase A: spectral-norm weights + projections =====
    {
        float* swt = sbuf;                 // 512
        float* swp = sbuf + 512;           // 512
        float* swg = sbuf + 1024;          // 2048
        block_sn(w_theta, u_theta, Cc, CK, swt, sv, su2, &ssig);
        block_sn(w_phi,   u_phi,   Cc, CK, swp, sv, su2, &ssig);
        block_sn(w_g,     u_g,     Cc, CG, swg, sv, su2, &ssig);

        // theta: one item per pixel (Bx*HW = 65536)
        for (int pix = gtid; pix < Bx * HW; pix += GSZ) {
            const float* xr = x + (size_t)pix * Cc;
            float a[CK];
            #pragma unroll
            for (int k = 0; k < CK; k++) a[k] = 0.f;
            #pragma unroll
            for (int c = 0; c < Cc; c++) {
                float xc = xr[c];
                #pragma unroll
                for (int k = 0; k < CK; k++) a[k] += xc * swt[c * CK + k];
            }
            #pragma unroll
            for (int k = 0; k < CK; k++) g_theta[(size_t)pix * CK + k] = a[k];
        }

        // phi: one item per pooled position (Bx*Mm = 16384)
        for (int idx = gtid; idx < Bx * Mm; idx += GSZ) {
            int b = idx / Mm, m = idx % Mm;
            int hp = m / (Ww / 2), wp = m % (Ww / 2);
            float p[CK];
            #pragma unroll
            for (int k = 0; k < CK; k++) p[k] = -1e30f;
            #pragma unroll
            for (int q = 0; q < 4; q++) {
                int n = (2 * hp + (q >> 1)) * Ww + (2 * wp + (q & 1));
                const float* xr = x + (size_t)(b * HW + n) * Cc;
                float s[CK];
                #pragma unroll
                for (int k = 0; k < CK; k++) s[k] = 0.f;
                #pragma unroll
                for (int c = 0; c < Cc; c++) {
                    float xc = xr[c];
                    #pragma unroll
                    for (int k = 0; k < CK; k++) s[k] += xc * swp[c * CK + k];
                }
                #pragma unroll
                for (int k = 0; k < CK; k++) p[k] = fmaxf(p[k], s[k]);
            }
            #pragma unroll
            for (int k = 0; k < CK; k++) g_phi[(size_t)idx * CK + k] = p[k];
        }

        // g: one item per (pooled position, 8-channel group) (Bx*Mm*4 = 65536)
        for (int t = gtid; t < Bx * Mm * 4; t += GSZ) {
            int grp = t & 3;
            int idx = t >> 2;
            int b = idx / Mm, m = idx % Mm;
            int hp = m / (Ww / 2), wp = m % (Ww / 2);
            int c0 = grp * 8;
            float p[8];
            #pragma unroll
            for (int k = 0; k < 8; k++) p[k] = -1e30f;
            #pragma unroll
            for (int q = 0; q < 4; q++) {
                int n = (2 * hp + (q >> 1)) * Ww + (2 * wp + (q & 1));
                const float* xr = x + (size_t)(b * HW + n) * Cc;
                float s[8];
                #pragma unroll
                for (int k = 0; k < 8; k++) s[k] = 0.f;
                #pragma unroll
                for (int c = 0; c < Cc; c++) {
                    float xc = xr[c];
                    #pragma unroll
                    for (int k = 0; k < 8; k++) s[k] += xc * swg[c * CG + c0 + k];
                }
                #pragma unroll
                for (int k = 0; k < 8; k++) p[k] = fmaxf(p[k], s[k]);
            }
            #pragma unroll
            for (int k = 0; k < 8; k++) g_gv[(size_t)idx * CG + c0 + k] = p[k];
        }
    }

    grid_barrier();

    // ===== Phase B: flash attention =====
    // Item = (query, 8-channel group): Bx*HW*4 = 262144 = 2 * GSZ.
    // Each block handles NT/4 = 128 consecutive queries per chunk (same
    // batch; 4096 % 128 == 0), staging 64-key phi/g tiles in smem.
    {
        float* sphi = sbuf;                // 64*CK  = 512
        float* sg   = sbuf + 512;          // 64*CG  = 2048

        for (int base = blockIdx.x * NT; base < Bx * HW * 4; base += GSZ) {
            int item = base + tid;
            int qidx = item >> 2;              // query
            int c0 = (item & 3) * 8;           // channel group
            int b = qidx / HW;

            float q[CK];
            #pragma unroll
            for (int k = 0; k < CK; k++) q[k] = g_theta[(size_t)qidx * CK + k];

            float mrun = -1e30f, lrun = 0.f;
            float acc[8];
            #pragma unroll
            for (int c = 0; c < 8; c++) acc[c] = 0.f;

            for (int kt = 0; kt < Mm / 64; kt++) {
                __syncthreads();
                const float* pbase = g_phi + (size_t)(b * Mm + kt * 64) * CK;
                const float* gbase = g_gv  + (size_t)(b * Mm + kt * 64) * CG;
                for (int i = tid; i < 64 * CK; i += NT) sphi[i] = pbase[i];
                for (int i = tid; i < 64 * CG; i += NT) sg[i]   = gbase[i];
                __syncthreads();

                for (int mm = 0; mm < 64; mm++) {
                    float s = 0.f;
                    #pragma unroll
                    for (int k = 0; k < CK; k++) s += q[k] * sphi[mm * CK + k];
                    float nm = fmaxf(mrun, s);
                    float corr = __expf(mrun - nm);
                    float e    = __expf(s - nm);
                    lrun = lrun * corr + e;
                    #pragma unroll
                    for (int c = 0; c < 8; c++)
                        acc[c] = acc[c] * corr + e * sg[mm * CG + c0 + c];
                    mrun = nm;
                }
            }
            float inv = 1.0f / lrun;
            #pragma unroll
            for (int c = 0; c < 8; c++)
                g_attng[(size_t)qidx * CG + c0 + c] = acc[c] * inv;
            __syncthreads();
        }
    }

    grid_barrier();

    // ===== Phase C: epilogue out = x + gamma * (attn_g @ Wbar_o) =====
    {
        float* swo = sbuf;                 // CG*Cc = 2048
        block_sn(w_o, u_o, CG, Cc, swo, sv, su2, &ssig);

        #pragma unroll
        for (int it = 0; it < 8; it++) {
            int t = gtid + it * GSZ;           // float4 index (8*GSZ total)
            float4 xv = xi[t];
            int i = t * 4;
            int pix = i / Cc;
            int c0  = i % Cc;
            const float* ar = g_attng + (size_t)pix * CG;
            float y0 = 0.f, y1 = 0.f, y2 = 0.f, y3 = 0.f;
            #pragma unroll
            for (int k = 0; k < CG; k++) {
                float a = ar[k];
                y0 += a * swo[k * Cc + c0];
                y1 += a * swo[k * Cc + c0 + 1];
                y2 += a * swo[k * Cc + c0 + 2];
                y3 += a * swo[k * Cc + c0 + 3];
            }
            oo[t] = make_float4(xv.x + gm * y0, xv.y + gm * y1,
                                xv.z + gm * y2, xv.w + gm * y3);
        }
    }
}

extern "C" void kernel_launch(void* const* d_in, const int* in_sizes, int n_in,
                              void* d_out, int out_size) {
    const float* x  = (const float*)d_in[0];
    const float* wt = (const float*)d_in[1]; const float* ut = (const float*)d_in[2];
    const float* wp = (const float*)d_in[3]; const float* up = (const float*)d_in[4];
    const float* wg = (const float*)d_in[5]; const float* ug = (const float*)d_in[6];
    const float* wo = (const float*)d_in[7]; const float* uo = (const float*)d_in[8];
    const float* gamma = (const float*)d_in[9];
    float* out = (float*)d_out;

    k_fused<<<NB, NT>>>(x, wt, ut, wp, up, wg, ug, wo, uo, gamma, out);
}

// round 15
// speedup vs baseline: 1.0037x; 1.0037x over previous
#include <cuda_runtime.h>

// SAGAN self-attention block:
//   out = x + gamma * conv_o( softmax(theta(x) @ phi(x)^T) @ g(x) )
// with spectral-normalized 1x1 convs and 2x2 maxpool on phi/g.
//
// FINAL converged kernel (5 consecutive benches in the 8.67-8.70us floor
// band). Floor model (R2-R14, 13 benches): wall = fixed graph-replay/launch
// cost (~6us, harness-side) + warm L2-rate 32MB copy (~2.7us structural
// minimum). All controllable axes swept with predicted deltas: node count
// (6/3/2/1 -- the only effective lever, 15.1 -> 8.67us), CTA count/shape,
// per-thread MLP, addressing, cache hints, CE memcpy, speculative prologue.
// Cold-profile kernel duration varied 8.2-12.1us across variants while wall
// stayed within 0.3us: wall is decoupled from SM-side copy micro-structure.
//
//   gamma == 0  -> out = x: gamma + first 4 float4 loads issued together
//                  (hides gamma's L2 hit), block-contiguous addressing
//                  (each block streams one 512KB region, warp-coalesced).
//   gamma != 0  -> persistent heavy path: per-block spectral-norm into smem,
//                  projections, software grid barrier (256 co-resident
//                  blocks), flash attention, barrier, output conv+residual.
//
// No per-thread array exceeds 8 statically-indexed floats -> no local-memory
// spill (harness counts driver local-pool growth as an allocation).

#define Bx 16
#define Hh 64
#define Ww 64
#define Cc 64
#define HW 4096     // Hh*Ww
#define Mm 1024     // pooled positions (HW/4)
#define CK 8        // Cc/8
#define CG 32       // Cc/2

#define NB 256      // blocks
#define NT 512      // threads per block
#define GSZ (NB * NT)          // 131072
#define CHUNK (8 * NT)         // float4s per block: 4096

__device__ float g_theta[(size_t)Bx * HW * CK];
__device__ float g_phi[(size_t)Bx * Mm * CK];
__device__ float g_gv[(size_t)Bx * Mm * CG];
__device__ float g_attng[(size_t)Bx * HW * CG];

__device__ unsigned int g_bar_cnt = 0;
__device__ unsigned int g_bar_gen = 0;

// Software grid barrier (all NB blocks co-resident). Self-resetting so graph
// replays are deterministic.
__device__ __forceinline__ void grid_barrier() {
    __syncthreads();
    if (threadIdx.x == 0) {
        volatile unsigned int* vgen = &g_bar_gen;
        unsigned int gen = *vgen;
        __threadfence();
        if (atomicAdd(&g_bar_cnt, 1u) == NB - 1) {
            g_bar_cnt = 0;
            __threadfence();
            atomicAdd(&g_bar_gen, 1u);
        } else {
            while (*vgen == gen) {}
        }
        __threadfence();
    }
    __syncthreads();
}

// Block-cooperative spectral normalization of one [d, co] weight into smem:
//   v = l2(W @ u); u2 = l2(W^T @ v); sigma = v . (W @ u2); wbar = W / sigma
__device__ __forceinline__ void block_sn(const float* __restrict__ w,
                                         const float* __restrict__ u,
                                         int d, int co,
                                         float* __restrict__ wbar,
                                         float* __restrict__ v,
                                         float* __restrict__ u2,
                                         float* __restrict__ sigma) {
    int tid = threadIdx.x;
    if (tid < d) {
        float s = 0.f;
        for (int j = 0; j < co; j++) s += w[tid * co + j] * u[j];
        v[tid] = s;
    }
    __syncthreads();
    if (tid == 0) {
        float nr = 0.f;
        for (int i = 0; i < d; i++) nr += v[i] * v[i];
        nr = sqrtf(nr) + 1e-12f;
        for (int i = 0; i < d; i++) v[i] /= nr;
    }
    __syncthreads();
    if (tid < co) {
        float s = 0.f;
        for (int i = 0; i < d; i++) s += w[i * co + tid] * v[i];
        u2[tid] = s;
    }
    __syncthreads();
    if (tid == 0) {
        float nr = 0.f;
        for (int j = 0; j < co; j++) nr += u2[j] * u2[j];
        nr = sqrtf(nr) + 1e-12f;
        float sig = 0.f;
        for (int i = 0; i < d; i++) {
            float t = 0.f;
            for (int j = 0; j < co; j++) t += w[i * co + j] * (u2[j] / nr);
            sig += v[i] * t;
        }
        *sigma = sig;
    }
    __syncthreads();
    float inv_sig = 1.0f / (*sigma);
    for (int e = tid; e < d * co; e += NT) wbar[e] = w[e] * inv_sig;
    __syncthreads();
}

__global__ void __launch_bounds__(NT) k_fused(
        const float* __restrict__ x,
        const float* __restrict__ w_theta, const float* __restrict__ u_theta,
        const float* __restrict__ w_phi,   const float* __restrict__ u_phi,
        const float* __restrict__ w_g,     const float* __restrict__ u_g,
        const float* __restrict__ w_o,     const float* __restrict__ u_o,
        const float* __restrict__ gamma,
        float* __restrict__ out) {
    const int tid = threadIdx.x;
    const int gtid = blockIdx.x * NT + tid;

    const float4* __restrict__ xi = reinterpret_cast<const float4*>(x);
    float4* __restrict__ oo = reinterpret_cast<float4*>(out);

    // Speculative prologue: gamma + first 4 block-contiguous loads in flight
    // together (loads are side-effect free; valid on both paths).
    const int cbase = blockIdx.x * CHUNK + tid;
    const float gm = gamma[0];
    float4 v0 = xi[cbase + 0 * NT];
    float4 v1 = xi[cbase + 1 * NT];
    float4 v2 = xi[cbase + 2 * NT];
    float4 v3 = xi[cbase + 3 * NT];
    // NB*CHUNK = 256*4096 = 1,048,576 = Bx*HW*Cc/4 exactly.

    if (gm == 0.0f) {
        // ---------- fast path: out = x, block-contiguous copy ----------
        oo[cbase + 0 * NT] = v0;
        oo[cbase + 1 * NT] = v1;
        float4 v4 = xi[cbase + 4 * NT];
        float4 v5 = xi[cbase + 5 * NT];
        float4 v6 = xi[cbase + 6 * NT];
        float4 v7 = xi[cbase + 7 * NT];
        oo[cbase + 2 * NT] = v2;
        oo[cbase + 3 * NT] = v3;
        oo[cbase + 4 * NT] = v4;
        oo[cbase + 5 * NT] = v5;
        oo[cbase + 6 * NT] = v6;
        oo[cbase + 7 * NT] = v7;
        return;
    }

    // ---------- heavy path (gamma != 0) ----------
    __shared__ float sbuf[3072];           // reused per phase (12 KB)
    __shared__ float sv[64], su2[64], ssig;

    // ===== Phase A: spectral-norm weights + projections =====
    {
        float* swt = sbuf;                 // 512
        float* swp = sbuf + 512;           // 512
        float* swg = sbuf + 1024;          // 2048
        block_sn(w_theta, u_theta, Cc, CK, swt, sv, su2, &ssig);
        block_sn(w_phi,   u_phi,   Cc, CK, swp, sv, su2, &ssig);
        block_sn(w_g,     u_g,     Cc, CG, swg, sv, su2, &ssig);

        // theta: one item per pixel (Bx*HW = 65536)
        for (int pix = gtid; pix < Bx * HW; pix += GSZ) {
            const float* xr = x + (size_t)pix * Cc;
            float a[CK];
            #pragma unroll
            for (int k = 0; k < CK; k++) a[k] = 0.f;
            #pragma unroll
            for (int c = 0; c < Cc; c++) {
                float xc = xr[c];
                #pragma unroll
                for (int k = 0; k < CK; k++) a[k] += xc * swt[c * CK + k];
            }
            #pragma unroll
            for (int k = 0; k < CK; k++) g_theta[(size_t)pix * CK + k] = a[k];
        }

        // phi: one item per pooled position (Bx*Mm = 16384)
        for (int idx = gtid; idx < Bx * Mm; idx += GSZ) {
            int b = idx / Mm, m = idx % Mm;
            int hp = m / (Ww / 2), wp = m % (Ww / 2);
            float p[CK];
            #pragma unroll
            for (int k = 0; k < CK; k++) p[k] = -1e30f;
            #pragma unroll
            for (int q = 0; q < 4; q++) {
                int n = (2 * hp + (q >> 1)) * Ww + (2 * wp + (q & 1));
                const float* xr = x + (size_t)(b * HW + n) * Cc;
                float s[CK];
                #pragma unroll
                for (int k = 0; k < CK; k++) s[k] = 0.f;
                #pragma unroll
                for (int c = 0; c < Cc; c++) {
                    float xc = xr[c];
                    #pragma unroll
                    for (int k = 0; k < CK; k++) s[k] += xc * swp[c * CK + k];
                }
                #pragma unroll
                for (int k = 0; k < CK; k++) p[k] = fmaxf(p[k], s[k]);
            }
            #pragma unroll
            for (int k = 0; k < CK; k++) g_phi[(size_t)idx * CK + k] = p[k];
        }

        // g: one item per (pooled position, 8-channel group) (Bx*Mm*4 = 65536)
        for (int t = gtid; t < Bx * Mm * 4; t += GSZ) {
            int grp = t & 3;
            int idx = t >> 2;
            int b = idx / Mm, m = idx % Mm;
            int hp = m / (Ww / 2), wp = m % (Ww / 2);
            int c0 = grp * 8;
            float p[8];
            #pragma unroll
            for (int k = 0; k < 8; k++) p[k] = -1e30f;
            #pragma unroll
            for (int q = 0; q < 4; q++) {
                int n = (2 * hp + (q >> 1)) * Ww + (2 * wp + (q & 1));
                const float* xr = x + (size_t)(b * HW + n) * Cc;
                float s[8];
                #pragma unroll
                for (int k = 0; k < 8; k++) s[k] = 0.f;
                #pragma unroll
                for (int c = 0; c < Cc; c++) {
                    float xc = xr[c];
                    #pragma unroll
                    for (int k = 0; k < 8; k++) s[k] += xc * swg[c * CG + c0 + k];
                }
                #pragma unroll
                for (int k = 0; k < 8; k++) p[k] = fmaxf(p[k], s[k]);
            }
            #pragma unroll
            for (int k = 0; k < 8; k++) g_gv[(size_t)idx * CG + c0 + k] = p[k];
        }
    }

    grid_barrier();

    // ===== Phase B: flash attention =====
    // Item = (query, 8-channel group): Bx*HW*4 = 262144 = 2 * GSZ.
    // Each block handles NT/4 = 128 consecutive queries per chunk (same
    // batch; 4096 % 128 == 0), staging 64-key phi/g tiles in smem.
    {
        float* sphi = sbuf;                // 64*CK  = 512
        float* sg   = sbuf + 512;          // 64*CG  = 2048

        for (int base = blockIdx.x * NT; base < Bx * HW * 4; base += GSZ) {
            int item = base + tid;
            int qidx = item >> 2;              // query
            int c0 = (item & 3) * 8;           // channel group
            int b = qidx / HW;

            float q[CK];
            #pragma unroll
            for (int k = 0; k < CK; k++) q[k] = g_theta[(size_t)qidx * CK + k];

            float mrun = -1e30f, lrun = 0.f;
            float acc[8];
            #pragma unroll
            for (int c = 0; c < 8; c++) acc[c] = 0.f;

            for (int kt = 0; kt < Mm / 64; kt++) {
                __syncthreads();
                const float* pbase = g_phi + (size_t)(b * Mm + kt * 64) * CK;
                const float* gbase = g_gv  + (size_t)(b * Mm + kt * 64) * CG;
                for (int i = tid; i < 64 * CK; i += NT) sphi[i] = pbase[i];
                for (int i = tid; i < 64 * CG; i += NT) sg[i]   = gbase[i];
                __syncthreads();

                for (int mm = 0; mm < 64; mm++) {
                    float s = 0.f;
                    #pragma unroll
                    for (int k = 0; k < CK; k++) s += q[k] * sphi[mm * CK + k];
                    float nm = fmaxf(mrun, s);
                    float corr = __expf(mrun - nm);
                    float e    = __expf(s - nm);
                    lrun = lrun * corr + e;
                    #pragma unroll
                    for (int c = 0; c < 8; c++)
                        acc[c] = acc[c] * corr + e * sg[mm * CG + c0 + c];
                    mrun = nm;
                }
            }
            float inv = 1.0f / lrun;
            #pragma unroll
            for (int c = 0; c < 8; c++)
                g_attng[(size_t)qidx * CG + c0 + c] = acc[c] * inv;
            __syncthreads();
        }
    }

    grid_barrier();

    // ===== Phase C: epilogue out = x + gamma * (attn_g @ Wbar_o) =====
    {
        float* swo = sbuf;                 // CG*Cc = 2048
        block_sn(w_o, u_o, CG, Cc, swo, sv, su2, &ssig);

        #pragma unroll
        for (int it = 0; it < 8; it++) {
            int t = gtid + it * GSZ;           // float4 index (8*GSZ total)
            float4 xv = xi[t];
            int i = t * 4;
            int pix = i / Cc;
            int c0  = i % Cc;
            const float* ar = g_attng + (size_t)pix * CG;
            float y0 = 0.f, y1 = 0.f, y2 = 0.f, y3 = 0.f;
            #pragma unroll
            for (int k = 0; k < CG; k++) {
                float a = ar[k];
                y0 += a * swo[k * Cc + c0];
                y1 += a * swo[k * Cc + c0 + 1];
                y2 += a * swo[k * Cc + c0 + 2];
                y3 += a * swo[k * Cc + c0 + 3];
            }
            oo[t] = make_float4(xv.x + gm * y0, xv.y + gm * y1,
                                xv.z + gm * y2, xv.w + gm * y3);
        }
    }
}

extern "C" void kernel_launch(void* const* d_in, const int* in_sizes, int n_in,
                              void* d_out, int out_size) {
    const float* x  = (const float*)d_in[0];
    const float* wt = (const float*)d_in[1]; const float* ut = (const float*)d_in[2];
    const float* wp = (const float*)d_in[3]; const float* up = (const float*)d_in[4];
    const float* wg = (const float*)d_in[5]; const float* ug = (const float*)d_in[6];
    const float* wo = (const float*)d_in[7]; const float* uo = (const float*)d_in[8];
    const float* gamma = (const float*)d_in[9];
    float* out = (float*)d_out;

    k_fused<<<NB, NT>>>(x, wt, ut, wp, up, wg, ug, wo, uo, gamma, out);
}

// round 16
// speedup vs baseline: 1.0502x; 1.0463x over previous
#include <cuda_runtime.h>

// SAGAN self-attention block:
//   out = x + gamma * conv_o( softmax(theta(x) @ phi(x)^T) @ g(x) )
// with spectral-normalized 1x1 convs and 2x2 maxpool on phi/g.
//
// Converged single-kernel design; floor = fixed graph-replay/launch cost
// (~6us) + warm L2-rate 32MB copy (~2.7us). R15 variant: the copy out=x is
// now UNCONDITIONAL (stores no longer wait on the gamma load + branch
// resolve -- the last exposed latency on the fast path). gamma gates only
// the heavy path, whose Phase C overwrites out with the correct residual
// result; the two grid barriers order all copies before any Phase C write.
// Work is identical on every call -> deterministic, graph-safe.
//
//   gamma == 0  -> copy only (return after).
//   gamma != 0  -> copy (dead but harmless) + persistent heavy path:
//                  per-block spectral-norm into smem, projections, grid
//                  barrier (256 co-resident blocks), flash attention,
//                  barrier, output conv + residual (overwrites out).
//
// No per-thread array exceeds 8 statically-indexed floats -> no local-memory
// spill (harness counts driver local-pool growth as an allocation).

#define Bx 16
#define Hh 64
#define Ww 64
#define Cc 64
#define HW 4096     // Hh*Ww
#define Mm 1024     // pooled positions (HW/4)
#define CK 8        // Cc/8
#define CG 32       // Cc/2

#define NB 256      // blocks
#define NT 512      // threads per block
#define GSZ (NB * NT)          // 131072
#define CHUNK (8 * NT)         // float4s per block: 4096

__device__ float g_theta[(size_t)Bx * HW * CK];
__device__ float g_phi[(size_t)Bx * Mm * CK];
__device__ float g_gv[(size_t)Bx * Mm * CG];
__device__ float g_attng[(size_t)Bx * HW * CG];

__device__ unsigned int g_bar_cnt = 0;
__device__ unsigned int g_bar_gen = 0;

// Software grid barrier (all NB blocks co-resident). Self-resetting so graph
// replays are deterministic.
__device__ __forceinline__ void grid_barrier() {
    __syncthreads();
    if (threadIdx.x == 0) {
        volatile unsigned int* vgen = &g_bar_gen;
        unsigned int gen = *vgen;
        __threadfence();
        if (atomicAdd(&g_bar_cnt, 1u) == NB - 1) {
            g_bar_cnt = 0;
            __threadfence();
            atomicAdd(&g_bar_gen, 1u);
        } else {
            while (*vgen == gen) {}
        }
        __threadfence();
    }
    __syncthreads();
}

// Block-cooperative spectral normalization of one [d, co] weight into smem:
//   v = l2(W @ u); u2 = l2(W^T @ v); sigma = v . (W @ u2); wbar = W / sigma
__device__ __forceinline__ void block_sn(const float* __restrict__ w,
                                         const float* __restrict__ u,
                                         int d, int co,
                                         float* __restrict__ wbar,
                                         float* __restrict__ v,
                                         float* __restrict__ u2,
                                         float* __restrict__ sigma) {
    int tid = threadIdx.x;
    if (tid < d) {
        float s = 0.f;
        for (int j = 0; j < co; j++) s += w[tid * co + j] * u[j];
        v[tid] = s;
    }
    __syncthreads();
    if (tid == 0) {
        float nr = 0.f;
        for (int i = 0; i < d; i++) nr += v[i] * v[i];
        nr = sqrtf(nr) + 1e-12f;
        for (int i = 0; i < d; i++) v[i] /= nr;
    }
    __syncthreads();
    if (tid < co) {
        float s = 0.f;
        for (int i = 0; i < d; i++) s += w[i * co + tid] * v[i];
        u2[tid] = s;
    }
    __syncthreads();
    if (tid == 0) {
        float nr = 0.f;
        for (int j = 0; j < co; j++) nr += u2[j] * u2[j];
        nr = sqrtf(nr) + 1e-12f;
        float sig = 0.f;
        for (int i = 0; i < d; i++) {
            float t = 0.f;
            for (int j = 0; j < co; j++) t += w[i * co + j] * (u2[j] / nr);
            sig += v[i] * t;
        }
        *sigma = sig;
    }
    __syncthreads();
    float inv_sig = 1.0f / (*sigma);
    for (int e = tid; e < d * co; e += NT) wbar[e] = w[e] * inv_sig;
    __syncthreads();
}

__global__ void __launch_bounds__(NT) k_fused(
        const float* __restrict__ x,
        const float* __restrict__ w_theta, const float* __restrict__ u_theta,
        const float* __restrict__ w_phi,   const float* __restrict__ u_phi,
        const float* __restrict__ w_g,     const float* __restrict__ u_g,
        const float* __restrict__ w_o,     const float* __restrict__ u_o,
        const float* __restrict__ gamma,
        float* __restrict__ out) {
    const int tid = threadIdx.x;
    const int gtid = blockIdx.x * NT + tid;

    const float4* __restrict__ xi = reinterpret_cast<const float4*>(x);
    float4* __restrict__ oo = reinterpret_cast<float4*>(out);

    // ---------- unconditional copy: out = x ----------
    // Block-contiguous (block b streams one 512KB region, warp-coalesced);
    // no dependence on gamma -- stores begin immediately. gamma load is
    // issued alongside so its latency overlaps the copy stream.
    const int cbase = blockIdx.x * CHUNK + tid;
    const float gm = gamma[0];
    {
        float4 v0 = xi[cbase + 0 * NT];
        float4 v1 = xi[cbase + 1 * NT];
        float4 v2 = xi[cbase + 2 * NT];
        float4 v3 = xi[cbase + 3 * NT];
        oo[cbase + 0 * NT] = v0;
        oo[cbase + 1 * NT] = v1;
        float4 v4 = xi[cbase + 4 * NT];
        float4 v5 = xi[cbase + 5 * NT];
        float4 v6 = xi[cbase + 6 * NT];
        float4 v7 = xi[cbase + 7 * NT];
        oo[cbase + 2 * NT] = v2;
        oo[cbase + 3 * NT] = v3;
        oo[cbase + 4 * NT] = v4;
        oo[cbase + 5 * NT] = v5;
        oo[cbase + 6 * NT] = v6;
        oo[cbase + 7 * NT] = v7;
    }
    // NB*CHUNK = 256*4096 = 1,048,576 = Bx*HW*Cc/4 exactly.

    if (gm == 0.0f) return;   // out = x is the final answer

    // ---------- heavy path (gamma != 0): overwrites out in Phase C ----------
    __shared__ float sbuf[3072];           // reused per phase (12 KB)
    __shared__ float sv[64], su2[64], ssig;

    // ===== Phase A: spectral-norm weights + projections =====
    {
        float* swt = sbuf;                 // 512
        float* swp = sbuf + 512;           // 512
        float* swg = sbuf + 1024;          // 2048
        block_sn(w_theta, u_theta, Cc, CK, swt, sv, su2, &ssig);
        block_sn(w_phi,   u_phi,   Cc, CK, swp, sv, su2, &ssig);
        block_sn(w_g,     u_g,     Cc, CG, swg, sv, su2, &ssig);

        // theta: one item per pixel (Bx*HW = 65536)
        for (int pix = gtid; pix < Bx * HW; pix += GSZ) {
            const float* xr = x + (size_t)pix * Cc;
            float a[CK];
            #pragma unroll
            for (int k = 0; k < CK; k++) a[k] = 0.f;
            #pragma unroll
            for (int c = 0; c < Cc; c++) {
                float xc = xr[c];
                #pragma unroll
                for (int k = 0; k < CK; k++) a[k] += xc * swt[c * CK + k];
            }
            #pragma unroll
            for (int k = 0; k < CK; k++) g_theta[(size_t)pix * CK + k] = a[k];
        }

        // phi: one item per pooled position (Bx*Mm = 16384)
        for (int idx = gtid; idx < Bx * Mm; idx += GSZ) {
            int b = idx / Mm, m = idx % Mm;
            int hp = m / (Ww / 2), wp = m % (Ww / 2);
            float p[CK];
            #pragma unroll
            for (int k = 0; k < CK; k++) p[k] = -1e30f;
            #pragma unroll
            for (int q = 0; q < 4; q++) {
                int n = (2 * hp + (q >> 1)) * Ww + (2 * wp + (q & 1));
                const float* xr = x + (size_t)(b * HW + n) * Cc;
                float s[CK];
                #pragma unroll
                for (int k = 0; k < CK; k++) s[k] = 0.f;
                #pragma unroll
                for (int c = 0; c < Cc; c++) {
                    float xc = xr[c];
                    #pragma unroll
                    for (int k = 0; k < CK; k++) s[k] += xc * swp[c * CK + k];
                }
                #pragma unroll
                for (int k = 0; k < CK; k++) p[k] = fmaxf(p[k], s[k]);
            }
            #pragma unroll
            for (int k = 0; k < CK; k++) g_phi[(size_t)idx * CK + k] = p[k];
        }

        // g: one item per (pooled position, 8-channel group) (Bx*Mm*4 = 65536)
        for (int t = gtid; t < Bx * Mm * 4; t += GSZ) {
            int grp = t & 3;
            int idx = t >> 2;
            int b = idx / Mm, m = idx % Mm;
            int hp = m / (Ww / 2), wp = m % (Ww / 2);
            int c0 = grp * 8;
            float p[8];
            #pragma unroll
            for (int k = 0; k < 8; k++) p[k] = -1e30f;
            #pragma unroll
            for (int q = 0; q < 4; q++) {
                int n = (2 * hp + (q >> 1)) * Ww + (2 * wp + (q & 1));
                const float* xr = x + (size_t)(b * HW + n) * Cc;
                float s[8];
                #pragma unroll
                for (int k = 0; k < 8; k++) s[k] = 0.f;
                #pragma unroll
                for (int c = 0; c < Cc; c++) {
                    float xc = xr[c];
                    #pragma unroll
                    for (int k = 0; k < 8; k++) s[k] += xc * swg[c * CG + c0 + k];
                }
                #pragma unroll
                for (int k = 0; k < 8; k++) p[k] = fmaxf(p[k], s[k]);
            }
            #pragma unroll
            for (int k = 0; k < 8; k++) g_gv[(size_t)idx * CG + c0 + k] = p[k];
        }
    }

    grid_barrier();   // also orders all blocks' copies before Phase C writes

    // ===== Phase B: flash attention =====
    // Item = (query, 8-channel group): Bx*HW*4 = 262144 = 2 * GSZ.
    // Each block handles NT/4 = 128 consecutive queries per chunk (same
    // batch; 4096 % 128 == 0), staging 64-key phi/g tiles in smem.
    {
        float* sphi = sbuf;                // 64*CK  = 512
        float* sg   = sbuf + 512;          // 64*CG  = 2048

        for (int base = blockIdx.x * NT; base < Bx * HW * 4; base += GSZ) {
            int item = base + tid;
            int qidx = item >> 2;              // query
            int c0 = (item & 3) * 8;           // channel group
            int b = qidx / HW;

            float q[CK];
            #pragma unroll
            for (int k = 0; k < CK; k++) q[k] = g_theta[(size_t)qidx * CK + k];

            float mrun = -1e30f, lrun = 0.f;
            float acc[8];
            #pragma unroll
            for (int c = 0; c < 8; c++) acc[c] = 0.f;

            for (int kt = 0; kt < Mm / 64; kt++) {
                __syncthreads();
                const float* pbase = g_phi + (size_t)(b * Mm + kt * 64) * CK;
                const float* gbase = g_gv  + (size_t)(b * Mm + kt * 64) * CG;
                for (int i = tid; i < 64 * CK; i += NT) sphi[i] = pbase[i];
                for (int i = tid; i < 64 * CG; i += NT) sg[i]   = gbase[i];
                __syncthreads();

                for (int mm = 0; mm < 64; mm++) {
                    float s = 0.f;
                    #pragma unroll
                    for (int k = 0; k < CK; k++) s += q[k] * sphi[mm * CK + k];
                    float nm = fmaxf(mrun, s);
                    float corr = __expf(mrun - nm);
                    float e    = __expf(s - nm);
                    lrun = lrun * corr + e;
                    #pragma unroll
                    for (int c = 0; c < 8; c++)
                        acc[c] = acc[c] * corr + e * sg[mm * CG + c0 + c];
                    mrun = nm;
                }
            }
            float inv = 1.0f / lrun;
            #pragma unroll
            for (int c = 0; c < 8; c++)
                g_attng[(size_t)qidx * CG + c0 + c] = acc[c] * inv;
            __syncthreads();
        }
    }

    grid_barrier();

    // ===== Phase C: epilogue out = x + gamma * (attn_g @ Wbar_o) =====
    // Overwrites the unconditional copy with the full correct value.
    {
        float* swo = sbuf;                 // CG*Cc = 2048
        block_sn(w_o, u_o, CG, Cc, swo, sv, su2, &ssig);

        #pragma unroll
        for (int it = 0; it < 8; it++) {
            int t = gtid + it * GSZ;           // float4 index (8*GSZ total)
            float4 xv = xi[t];
            int i = t * 4;
            int pix = i / Cc;
            int c0  = i % Cc;
            const float* ar = g_attng + (size_t)pix * CG;
            float y0 = 0.f, y1 = 0.f, y2 = 0.f, y3 = 0.f;
            #pragma unroll
            for (int k = 0; k < CG; k++) {
                float a = ar[k];
                y0 += a * swo[k * Cc + c0];
                y1 += a * swo[k * Cc + c0 + 1];
                y2 += a * swo[k * Cc + c0 + 2];
                y3 += a * swo[k * Cc + c0 + 3];
            }
            oo[t] = make_float4(xv.x + gm * y0, xv.y + gm * y1,
                                xv.z + gm * y2, xv.w + gm * y3);
        }
    }
}

extern "C" void kernel_launch(void* const* d_in, const int* in_sizes, int n_in,
                              void* d_out, int out_size) {
    const float* x  = (const float*)d_in[0];
    const float* wt = (const float*)d_in[1]; const float* ut = (const float*)d_in[2];
    const float* wp = (const float*)d_in[3]; const float* up = (const float*)d_in[4];
    const float* wg = (const float*)d_in[5]; const float* ug = (const float*)d_in[6];
    const float* wo = (const float*)d_in[7]; const float* uo = (const float*)d_in[8];
    const float* gamma = (const float*)d_in[9];
    float* out = (float*)d_out;

    k_fused<<<NB, NT>>>(x, wt, ut, wp, up, wg, ug, wo, uo, gamma, out);
}